// round 1
// baseline (speedup 1.0000x reference)
#include <cuda_runtime.h>
#include <math.h>

// Problem constants
// B=4, C=64, H=W=256, N_SPLIT=4 (T=16), RED_FC=32, OUT_NC=32, K=3, FMN1=FMN2=2048
// wsize = 32*64*9 = 18432, wb row = 18464

// ---------------- scratch (device globals; no runtime allocation) ----------
__device__ float g_h[4*64*256*256];       // conv1 output (leaky-relu'd)
__device__ float g_adap[4*256*256];       // tanh(conv2)
__device__ float g_gram[64*1024];         // pooled grams
__device__ float g_fc1[64*2048];
__device__ float g_fc2[64*2048];
__device__ float g_wb[64*18464];          // dynamic weights + bias

// ---------------- f32x2 helpers (sm_103a packed fp32 FMA) ------------------
__device__ __forceinline__ unsigned long long pack2(float lo, float hi) {
    unsigned long long d;
    asm("mov.b64 %0, {%1, %2};" : "=l"(d) : "f"(lo), "f"(hi));
    return d;
}
__device__ __forceinline__ void unpack2(unsigned long long d, float& lo, float& hi) {
    asm("mov.b64 {%0, %1}, %2;" : "=f"(lo), "=f"(hi) : "l"(d));
}
__device__ __forceinline__ unsigned long long fma2(unsigned long long a,
                                                   unsigned long long b,
                                                   unsigned long long c) {
    unsigned long long d;
    asm("fma.rn.f32x2 %0, %1, %2, %3;" : "=l"(d) : "l"(a), "l"(b), "l"(c));
    return d;
}

// ---------------- conv1: 64->64 3x3 pad1 + leaky relu ----------------------
// grid (8,8,32): x-tile, y-tile, z = b*8 + ocg (8 output chans per block)
// block (32,8): each thread computes 4 pixels (rows ty, ty+8, ty+16, ty+24)
__global__ __launch_bounds__(256) void conv1_kernel(
    const float* __restrict__ feat,
    const float* __restrict__ rw1,
    const float* __restrict__ rb1)
{
    __shared__ unsigned long long wsm[8*64*9];   // splatted (w,w) pairs, 36 KB
    __shared__ float patch[34][34];

    int b = blockIdx.z >> 3, ocg = blockIdx.z & 7;
    int x0 = blockIdx.x * 32, y0 = blockIdx.y * 32;
    int tx = threadIdx.x, ty = threadIdx.y;
    int tid = ty * 32 + tx;

    const float* wbase = rw1 + ocg * (8*64*9);
    for (int i = tid; i < 8*64*9; i += 256) {
        float w = wbase[i];
        wsm[i] = pack2(w, w);
    }

    unsigned long long accA[8], accB[8];
#pragma unroll
    for (int o = 0; o < 8; o++) { accA[o] = 0ull; accB[o] = 0ull; }

    for (int ic = 0; ic < 64; ic++) {
        __syncthreads();
        const float* fp = feat + (size_t)(b*64 + ic) * 65536;
        for (int i = tid; i < 34*34; i += 256) {
            int py = i / 34, px = i % 34;
            int gy = y0 - 1 + py, gx = x0 - 1 + px;
            float v = 0.f;
            if ((unsigned)gy < 256u && (unsigned)gx < 256u) v = fp[gy*256 + gx];
            patch[py][px] = v;
        }
        __syncthreads();

        unsigned long long PA[9], PB[9];
#pragma unroll
        for (int dy = 0; dy < 3; dy++)
#pragma unroll
            for (int dx = 0; dx < 3; dx++) {
                int k = dy*3 + dx;
                PA[k] = pack2(patch[ty + dy][tx + dx],      patch[ty + 8  + dy][tx + dx]);
                PB[k] = pack2(patch[ty + 16 + dy][tx + dx], patch[ty + 24 + dy][tx + dx]);
            }
#pragma unroll
        for (int o = 0; o < 8; o++) {
            const unsigned long long* w = &wsm[(o*64 + ic) * 9];
#pragma unroll
            for (int k = 0; k < 9; k++) {
                unsigned long long w2 = w[k];
                accA[o] = fma2(PA[k], w2, accA[o]);
                accB[o] = fma2(PB[k], w2, accB[o]);
            }
        }
    }

#pragma unroll
    for (int o = 0; o < 8; o++) {
        int oc = ocg*8 + o;
        float bias = rb1[oc];
        float v0, v1, v2, v3;
        unpack2(accA[o], v0, v1);
        unpack2(accB[o], v2, v3);
        float vv[4] = {v0, v1, v2, v3};
        size_t base = (size_t)(b*64 + oc) * 65536;
#pragma unroll
        for (int k = 0; k < 4; k++) {
            float v = vv[k] + bias;
            v = (v >= 0.f) ? v : 0.2f * v;
            g_h[base + (size_t)(y0 + ty + 8*k) * 256 + x0 + tx] = v;
        }
    }
}

// ---------------- conv2: 64->1 3x3 pad1 + tanh -----------------------------
__global__ __launch_bounds__(256) void conv2_kernel(
    const float* __restrict__ rw2, const float* __restrict__ rb2)
{
    __shared__ float wsm[576];
    __shared__ float patch[34][34];
    int b = blockIdx.z;
    int x0 = blockIdx.x * 32, y0 = blockIdx.y * 32;
    int tx = threadIdx.x, ty = threadIdx.y;
    int tid = ty * 32 + tx;
    for (int i = tid; i < 576; i += 256) wsm[i] = rw2[i];
    float acc[4] = {0.f, 0.f, 0.f, 0.f};

    for (int ic = 0; ic < 64; ic++) {
        __syncthreads();
        const float* fp = g_h + (size_t)(b*64 + ic) * 65536;
        for (int i = tid; i < 34*34; i += 256) {
            int py = i / 34, px = i % 34;
            int gy = y0 - 1 + py, gx = x0 - 1 + px;
            float v = 0.f;
            if ((unsigned)gy < 256u && (unsigned)gx < 256u) v = fp[gy*256 + gx];
            patch[py][px] = v;
        }
        __syncthreads();
#pragma unroll
        for (int k = 0; k < 4; k++) {
            float s = acc[k];
#pragma unroll
            for (int dy = 0; dy < 3; dy++)
#pragma unroll
                for (int dx = 0; dx < 3; dx++)
                    s += patch[ty + 8*k + dy][tx + dx] * wsm[ic*9 + dy*3 + dx];
            acc[k] = s;
        }
    }
    float bias = rb2[0];
#pragma unroll
    for (int k = 0; k < 4; k++)
        g_adap[((size_t)b*256 + y0 + ty + 8*k) * 256 + x0 + tx] = tanhf(acc[k] + bias);
}

// ---------------- adaptive pool per tile -> gram ---------------------------
// grid 64 (= b*16 + t), 256 threads. Window 66x66 with zero pad at image edge.
__global__ void pool_kernel()
{
    __shared__ float win[66][67];
    int r = blockIdx.x;
    int b = r >> 4, t = r & 15;
    int ti = t >> 2, tj = t & 3;
    int tid = threadIdx.x;
    for (int i = tid; i < 66*66; i += 256) {
        int h = i / 66, w = i % 66;
        int gy = ti*64 - 1 + h, gx = tj*64 - 1 + w;
        float v = 0.f;
        if ((unsigned)gy < 256u && (unsigned)gx < 256u)
            v = g_adap[((size_t)b*256 + gy) * 256 + gx];
        win[h][w] = v;
    }
    __syncthreads();
    for (int i = tid; i < 1024; i += 256) {
        int p = i >> 5, q = i & 31;
        int sp = (p*66) >> 5, ep = ((p+1)*66 + 31) >> 5;
        int sq = (q*66) >> 5, eq = ((q+1)*66 + 31) >> 5;
        float s = 0.f;
        for (int h = sp; h < ep; h++)
            for (int w = sq; w < eq; w++)
                s += win[h][w];
        g_gram[r*1024 + i] = s / (float)((ep - sp) * (eq - sq));
    }
}

// ---------------- FC GEMM: Out(64xN) = act(A(64xK) @ B(KxN) + bias) --------
// stage: 0: gram->fc1 (relu), 1: fc1->fc2 (relu), 2: fc2->wb (linear)
__global__ __launch_bounds__(256) void gemm_kernel(
    const float* __restrict__ Bm, const float* __restrict__ bias,
    int K, int N, int stage, int do_relu)
{
    const float* A = (stage == 0) ? g_gram : (stage == 1) ? g_fc1 : g_fc2;
    float* Out     = (stage == 0) ? g_fc1  : (stage == 1) ? g_fc2 : g_wb;

    __shared__ float As[16][64];
    __shared__ float Bs[16][64];
    int tid = threadIdx.x;
    int tx = tid & 15, ty = tid >> 4;
    int n0 = blockIdx.x * 64;
    float acc[4][4] = {};

    for (int k0 = 0; k0 < K; k0 += 16) {
        __syncthreads();
        for (int i = tid; i < 1024; i += 256) {
            int m = i & 63, kk = i >> 6;
            As[kk][m] = A[m*K + k0 + kk];
            int col = n0 + m;
            Bs[kk][m] = (col < N) ? Bm[(size_t)(k0 + kk)*N + col] : 0.f;
        }
        __syncthreads();
#pragma unroll
        for (int kk = 0; kk < 16; kk++) {
            float a[4], bv[4];
#pragma unroll
            for (int u = 0; u < 4; u++) a[u]  = As[kk][ty*4 + u];
#pragma unroll
            for (int v = 0; v < 4; v++) bv[v] = Bs[kk][tx*4 + v];
#pragma unroll
            for (int u = 0; u < 4; u++)
#pragma unroll
                for (int v = 0; v < 4; v++)
                    acc[u][v] += a[u] * bv[v];
        }
    }

#pragma unroll
    for (int u = 0; u < 4; u++) {
        int row = ty*4 + u;
#pragma unroll
        for (int v = 0; v < 4; v++) {
            int col = n0 + tx*4 + v;
            if (col < N) {
                float x = acc[u][v] + bias[col];
                if (do_relu) x = fmaxf(x, 0.f);
                Out[(size_t)row*N + col] = x;
            }
        }
    }
}

// ---------------- dynamic per-tile conv (64->32, VALID on 66x66 window) ----
// grid (2,2,256): quadrant x, quadrant y, z = (b*16+t)*4 + ocg (8 oc/block)
__global__ __launch_bounds__(256) void dynconv_kernel(
    const float* __restrict__ feat, float* __restrict__ out)
{
    __shared__ unsigned long long wsm[8*64*9];
    __shared__ float patch[34][34];

    int idx = blockIdx.z;
    int ocg = idx & 3;
    int r = idx >> 2;                       // b*16 + t
    int b = r >> 4, t = r & 15;
    int ti = t >> 2, tj = t & 3;
    int gy0 = ti*64 + blockIdx.y * 32;
    int gx0 = tj*64 + blockIdx.x * 32;
    int tx = threadIdx.x, ty = threadIdx.y;
    int tid = ty * 32 + tx;

    const float* wrow = g_wb + (size_t)r * 18464 + ocg * (8*576);
    for (int i = tid; i < 4608; i += 256) {
        float w = wrow[i];
        wsm[i] = pack2(w, w);
    }

    unsigned long long accA[8], accB[8];
#pragma unroll
    for (int o = 0; o < 8; o++) { accA[o] = 0ull; accB[o] = 0ull; }

    for (int ic = 0; ic < 64; ic++) {
        __syncthreads();
        const float* fp = feat + (size_t)(b*64 + ic) * 65536;
        for (int i = tid; i < 34*34; i += 256) {
            int py = i / 34, px = i % 34;
            int gy = gy0 - 1 + py, gx = gx0 - 1 + px;
            float v = 0.f;
            if ((unsigned)gy < 256u && (unsigned)gx < 256u) v = fp[gy*256 + gx];
            patch[py][px] = v;
        }
        __syncthreads();

        unsigned long long PA[9], PB[9];
#pragma unroll
        for (int dy = 0; dy < 3; dy++)
#pragma unroll
            for (int dx = 0; dx < 3; dx++) {
                int k = dy*3 + dx;
                PA[k] = pack2(patch[ty + dy][tx + dx],      patch[ty + 8  + dy][tx + dx]);
                PB[k] = pack2(patch[ty + 16 + dy][tx + dx], patch[ty + 24 + dy][tx + dx]);
            }
#pragma unroll
        for (int o = 0; o < 8; o++) {
            const unsigned long long* w = &wsm[(o*64 + ic) * 9];
#pragma unroll
            for (int k = 0; k < 9; k++) {
                unsigned long long w2 = w[k];
                accA[o] = fma2(PA[k], w2, accA[o]);
                accB[o] = fma2(PB[k], w2, accB[o]);
            }
        }
    }

#pragma unroll
    for (int o = 0; o < 8; o++) {
        int oc = ocg*8 + o;
        float bias = g_wb[(size_t)r * 18464 + 18432 + oc];
        float v0, v1, v2, v3;
        unpack2(accA[o], v0, v1);
        unpack2(accB[o], v2, v3);
        float vv[4] = {v0, v1, v2, v3};
        size_t base = (size_t)(b*96 + 64 + oc) * 65536;
#pragma unroll
        for (int k = 0; k < 4; k++)
            out[base + (size_t)(gy0 + ty + 8*k) * 256 + gx0 + tx] = vv[k] + bias;
    }
}

// ---------------- passthrough copy: out[:, 0:64] = feature -----------------
__global__ void copy_feat_kernel(const float4* __restrict__ f, float4* __restrict__ out)
{
    int i = blockIdx.x * 256 + threadIdx.x;    // 4,194,304 float4 total
    if (i < 4194304) {
        int b = i >> 20;                        // 1,048,576 float4 per batch (64 ch)
        int rem = i & ((1 << 20) - 1);
        out[(size_t)b * 1572864 + rem] = f[i];  // 96 ch * 65536 / 4 per batch
    }
}

// ---------------- launch ---------------------------------------------------
extern "C" void kernel_launch(void* const* d_in, const int* in_sizes, int n_in,
                              void* d_out, int out_size)
{
    const float* feature = (const float*)d_in[0];
    const float* rw1 = (const float*)d_in[1];
    const float* rb1 = (const float*)d_in[2];
    const float* rw2 = (const float*)d_in[3];
    const float* rb2 = (const float*)d_in[4];
    const float* fw1 = (const float*)d_in[5];
    const float* fb1 = (const float*)d_in[6];
    const float* fw2 = (const float*)d_in[7];
    const float* fb2 = (const float*)d_in[8];
    const float* fw3 = (const float*)d_in[9];
    const float* fb3 = (const float*)d_in[10];
    float* out = (float*)d_out;

    conv1_kernel<<<dim3(8, 8, 32), dim3(32, 8)>>>(feature, rw1, rb1);
    conv2_kernel<<<dim3(8, 8, 4),  dim3(32, 8)>>>(rw2, rb2);
    pool_kernel<<<64, 256>>>();
    gemm_kernel<<<32,  256>>>(fw1, fb1, 1024, 2048, 0, 1);
    gemm_kernel<<<32,  256>>>(fw2, fb2, 2048, 2048, 1, 1);
    gemm_kernel<<<289, 256>>>(fw3, fb3, 2048, 18464, 2, 0);
    dynconv_kernel<<<dim3(2, 2, 256), dim3(32, 8)>>>(feature, out);
    copy_feat_kernel<<<16384, 256>>>((const float4*)feature, (float4*)out);
}

// round 2
// speedup vs baseline: 1.3824x; 1.3824x over previous
#include <cuda_runtime.h>
#include <math.h>

// Problem constants
// B=4, C=64, H=W=256, N_SPLIT=4 (T=16), RED_FC=32, OUT_NC=32, K=3, FMN1=FMN2=2048
// wsize = 32*64*9 = 18432, wb row = 18464

typedef unsigned long long ull;

// ---------------- scratch (device globals; no runtime allocation) ----------
__device__ float g_h[4*64*256*256];       // conv1 output (leaky-relu'd)
__device__ float g_adap[4*256*256];       // tanh(conv2)
__device__ float g_gram[64*1024];         // pooled grams
__device__ float g_fc1[64*2048];
__device__ float g_fc2[64*2048];
__device__ float g_wb[64*18464];          // dynamic weights + bias
__device__ float g_part[2363392];         // split-K partials (max: 2 x 64 x 18464)

// ---------------- f32x2 helpers (sm_103a packed fp32 FMA) ------------------
__device__ __forceinline__ ull pack2(float lo, float hi) {
    ull d;
    asm("mov.b64 %0, {%1, %2};" : "=l"(d) : "f"(lo), "f"(hi));
    return d;
}
__device__ __forceinline__ void unpack2(ull d, float& lo, float& hi) {
    asm("mov.b64 {%0, %1}, %2;" : "=f"(lo), "=f"(hi) : "l"(d));
}
__device__ __forceinline__ ull fma2(ull a, ull b, ull c) {
    ull d;
    asm("fma.rn.f32x2 %0, %1, %2, %3;" : "=l"(d) : "l"(a), "l"(b), "l"(c));
    return d;
}

// ---------------- conv1: 64->64 3x3 pad1 + leaky relu ----------------------
// grid (8,8,32): x-tile, y-tile, z = b*8 + ocg (8 output chans per block)
// block (32,8): each thread computes 4 pixels (rows ty, ty+8, ty+16, ty+24)
__global__ __launch_bounds__(256) void conv1_kernel(
    const float* __restrict__ feat,
    const float* __restrict__ rw1,
    const float* __restrict__ rb1)
{
    __shared__ ull wsm[8*64*9];   // splatted (w,w) pairs, 36 KB
    __shared__ float patch[34][34];

    int b = blockIdx.z >> 3, ocg = blockIdx.z & 7;
    int x0 = blockIdx.x * 32, y0 = blockIdx.y * 32;
    int tx = threadIdx.x, ty = threadIdx.y;
    int tid = ty * 32 + tx;

    const float* wbase = rw1 + ocg * (8*64*9);
    for (int i = tid; i < 8*64*9; i += 256) {
        float w = wbase[i];
        wsm[i] = pack2(w, w);
    }

    ull accA[8], accB[8];
#pragma unroll
    for (int o = 0; o < 8; o++) { accA[o] = 0ull; accB[o] = 0ull; }

    for (int ic = 0; ic < 64; ic++) {
        __syncthreads();
        const float* fp = feat + (size_t)(b*64 + ic) * 65536;
        for (int i = tid; i < 34*34; i += 256) {
            int py = i / 34, px = i % 34;
            int gy = y0 - 1 + py, gx = x0 - 1 + px;
            float v = 0.f;
            if ((unsigned)gy < 256u && (unsigned)gx < 256u) v = fp[gy*256 + gx];
            patch[py][px] = v;
        }
        __syncthreads();

        ull PA[9], PB[9];
#pragma unroll
        for (int dy = 0; dy < 3; dy++)
#pragma unroll
            for (int dx = 0; dx < 3; dx++) {
                int k = dy*3 + dx;
                PA[k] = pack2(patch[ty + dy][tx + dx],      patch[ty + 8  + dy][tx + dx]);
                PB[k] = pack2(patch[ty + 16 + dy][tx + dx], patch[ty + 24 + dy][tx + dx]);
            }
#pragma unroll
        for (int o = 0; o < 8; o++) {
            const ull* w = &wsm[(o*64 + ic) * 9];
#pragma unroll
            for (int k = 0; k < 9; k++) {
                ull w2 = w[k];
                accA[o] = fma2(PA[k], w2, accA[o]);
                accB[o] = fma2(PB[k], w2, accB[o]);
            }
        }
    }

#pragma unroll
    for (int o = 0; o < 8; o++) {
        int oc = ocg*8 + o;
        float bias = rb1[oc];
        float v0, v1, v2, v3;
        unpack2(accA[o], v0, v1);
        unpack2(accB[o], v2, v3);
        float vv[4] = {v0, v1, v2, v3};
        size_t base = (size_t)(b*64 + oc) * 65536;
#pragma unroll
        for (int k = 0; k < 4; k++) {
            float v = vv[k] + bias;
            v = (v >= 0.f) ? v : 0.2f * v;
            g_h[base + (size_t)(y0 + ty + 8*k) * 256 + x0 + tx] = v;
        }
    }
}

// ---------------- conv2: 64->1 3x3 pad1 + tanh -----------------------------
__global__ __launch_bounds__(256) void conv2_kernel(
    const float* __restrict__ rw2, const float* __restrict__ rb2)
{
    __shared__ float wsm[576];
    __shared__ float patch[34][34];
    int b = blockIdx.z;
    int x0 = blockIdx.x * 32, y0 = blockIdx.y * 32;
    int tx = threadIdx.x, ty = threadIdx.y;
    int tid = ty * 32 + tx;
    for (int i = tid; i < 576; i += 256) wsm[i] = rw2[i];
    float acc[4] = {0.f, 0.f, 0.f, 0.f};

    for (int ic = 0; ic < 64; ic++) {
        __syncthreads();
        const float* fp = g_h + (size_t)(b*64 + ic) * 65536;
        for (int i = tid; i < 34*34; i += 256) {
            int py = i / 34, px = i % 34;
            int gy = y0 - 1 + py, gx = x0 - 1 + px;
            float v = 0.f;
            if ((unsigned)gy < 256u && (unsigned)gx < 256u) v = fp[gy*256 + gx];
            patch[py][px] = v;
        }
        __syncthreads();
#pragma unroll
        for (int k = 0; k < 4; k++) {
            float s = acc[k];
#pragma unroll
            for (int dy = 0; dy < 3; dy++)
#pragma unroll
                for (int dx = 0; dx < 3; dx++)
                    s += patch[ty + 8*k + dy][tx + dx] * wsm[ic*9 + dy*3 + dx];
            acc[k] = s;
        }
    }
    float bias = rb2[0];
#pragma unroll
    for (int k = 0; k < 4; k++)
        g_adap[((size_t)b*256 + y0 + ty + 8*k) * 256 + x0 + tx] = tanhf(acc[k] + bias);
}

// ---------------- adaptive pool per tile -> gram ---------------------------
__global__ void pool_kernel()
{
    __shared__ float win[66][67];
    int r = blockIdx.x;
    int b = r >> 4, t = r & 15;
    int ti = t >> 2, tj = t & 3;
    int tid = threadIdx.x;
    for (int i = tid; i < 66*66; i += 256) {
        int h = i / 66, w = i % 66;
        int gy = ti*64 - 1 + h, gx = tj*64 - 1 + w;
        float v = 0.f;
        if ((unsigned)gy < 256u && (unsigned)gx < 256u)
            v = g_adap[((size_t)b*256 + gy) * 256 + gx];
        win[h][w] = v;
    }
    __syncthreads();
    for (int i = tid; i < 1024; i += 256) {
        int p = i >> 5, q = i & 31;
        int sp = (p*66) >> 5, ep = ((p+1)*66 + 31) >> 5;
        int sq = (q*66) >> 5, eq = ((q+1)*66 + 31) >> 5;
        float s = 0.f;
        for (int h = sp; h < ep; h++)
            for (int w = sq; w < eq; w++)
                s += win[h][w];
        g_gram[r*1024 + i] = s / (float)((ep - sp) * (eq - sq));
    }
}

// ---------------- split-K GEMM: part[s] = A(64xKC chunk) @ B ---------------
// grid (ceil(N/64), nsplit), block 128. Thread tile: 4 M-rows x 8 N-cols
// via f32x2 (4x4 packed accumulators).
__global__ __launch_bounds__(128) void gemm_sk_kernel(
    const float* __restrict__ Bm, int K, int N, int KC, int stage)
{
    const float* __restrict__ A = (stage == 0) ? g_gram : (stage == 1) ? g_fc1 : g_fc2;

    __shared__ float  As[16][65];
    __shared__ float4 Bs[16][16];

    int n0 = blockIdx.x * 64;
    int k0 = blockIdx.y * KC;
    int tid = threadIdx.x;
    int tx = tid & 7;        // 8 col groups of 8
    int ty = tid >> 3;       // 16 row groups of 4

    ull acc[4][4];
#pragma unroll
    for (int u = 0; u < 4; u++)
#pragma unroll
        for (int v = 0; v < 4; v++) acc[u][v] = 0ull;

    for (int kc = 0; kc < KC; kc += 16) {
        int kb = k0 + kc;
        __syncthreads();
        // A: 64 rows x 16 k -> transpose into As[kk][m]; 256 float4, 2/thread
#pragma unroll
        for (int r = 0; r < 2; r++) {
            int i = tid * 2 + r;
            int m  = i >> 2;
            int kg = (i & 3) * 4;
            float4 v = *(const float4*)&A[(size_t)m * K + kb + kg];
            As[kg+0][m] = v.x; As[kg+1][m] = v.y;
            As[kg+2][m] = v.z; As[kg+3][m] = v.w;
        }
        // B: 16 kk x 64 n; 256 float4, 2/thread (guard N tail, N % 4 == 0)
#pragma unroll
        for (int r = 0; r < 2; r++) {
            int i = tid * 2 + r;
            int kk = i >> 4;
            int f  = i & 15;
            int col = n0 + f * 4;
            float4 v = make_float4(0.f, 0.f, 0.f, 0.f);
            if (col < N) v = *(const float4*)&Bm[(size_t)(kb + kk) * N + col];
            Bs[kk][f] = v;
        }
        __syncthreads();

#pragma unroll
        for (int kk = 0; kk < 16; kk++) {
            ull a2[4];
#pragma unroll
            for (int u = 0; u < 4; u++) {
                float a = As[kk][ty*4 + u];
                a2[u] = pack2(a, a);
            }
            const ull* bp = (const ull*)&Bs[kk][tx*2];
            ull b2[4];
#pragma unroll
            for (int v = 0; v < 4; v++) b2[v] = bp[v];
#pragma unroll
            for (int u = 0; u < 4; u++)
#pragma unroll
                for (int v = 0; v < 4; v++)
                    acc[u][v] = fma2(b2[v], a2[u], acc[u][v]);
        }
    }

    int s = blockIdx.y;
#pragma unroll
    for (int u = 0; u < 4; u++) {
        int row = ty*4 + u;
#pragma unroll
        for (int v = 0; v < 4; v++) {
            int col = n0 + tx*8 + v*2;
            if (col < N) {       // col even, N even -> covers col+1 too
                float lo, hi;
                unpack2(acc[u][v], lo, hi);
                float* p = &g_part[((size_t)(s*64 + row)) * N + col];
                p[0] = lo; p[1] = hi;
            }
        }
    }
}

// ---------------- split-K reduce + bias + activation -----------------------
__global__ void gemm_reduce_kernel(const float* __restrict__ bias,
                                   int N, int nsplit, int relu, int stage)
{
    float* out = (stage == 0) ? g_fc1 : (stage == 1) ? g_fc2 : g_wb;
    int nv = N >> 2;
    int idx = blockIdx.x * 256 + threadIdx.x;
    if (idx >= 64 * nv) return;
    int m = idx / nv, f = idx - m * nv;
    float4 s = make_float4(0.f, 0.f, 0.f, 0.f);
    for (int sp = 0; sp < nsplit; sp++) {
        const float4* p = (const float4*)&g_part[(size_t)(sp*64 + m) * N];
        float4 v = p[f];
        s.x += v.x; s.y += v.y; s.z += v.z; s.w += v.w;
    }
    float4 bv = ((const float4*)bias)[f];
    s.x += bv.x; s.y += bv.y; s.z += bv.z; s.w += bv.w;
    if (relu) {
        s.x = fmaxf(s.x, 0.f); s.y = fmaxf(s.y, 0.f);
        s.z = fmaxf(s.z, 0.f); s.w = fmaxf(s.w, 0.f);
    }
    ((float4*)out)[(size_t)m * nv + f] = s;
}

// ---------------- dynamic per-tile conv (64->32, VALID on 66x66 window) ----
__global__ __launch_bounds__(256) void dynconv_kernel(
    const float* __restrict__ feat, float* __restrict__ out)
{
    __shared__ ull wsm[8*64*9];
    __shared__ float patch[34][34];

    int idx = blockIdx.z;
    int ocg = idx & 3;
    int r = idx >> 2;                       // b*16 + t
    int b = r >> 4, t = r & 15;
    int ti = t >> 2, tj = t & 3;
    int gy0 = ti*64 + blockIdx.y * 32;
    int gx0 = tj*64 + blockIdx.x * 32;
    int tx = threadIdx.x, ty = threadIdx.y;
    int tid = ty * 32 + tx;

    const float* wrow = g_wb + (size_t)r * 18464 + ocg * (8*576);
    for (int i = tid; i < 4608; i += 256) {
        float w = wrow[i];
        wsm[i] = pack2(w, w);
    }

    ull accA[8], accB[8];
#pragma unroll
    for (int o = 0; o < 8; o++) { accA[o] = 0ull; accB[o] = 0ull; }

    for (int ic = 0; ic < 64; ic++) {
        __syncthreads();
        const float* fp = feat + (size_t)(b*64 + ic) * 65536;
        for (int i = tid; i < 34*34; i += 256) {
            int py = i / 34, px = i % 34;
            int gy = gy0 - 1 + py, gx = gx0 - 1 + px;
            float v = 0.f;
            if ((unsigned)gy < 256u && (unsigned)gx < 256u) v = fp[gy*256 + gx];
            patch[py][px] = v;
        }
        __syncthreads();

        ull PA[9], PB[9];
#pragma unroll
        for (int dy = 0; dy < 3; dy++)
#pragma unroll
            for (int dx = 0; dx < 3; dx++) {
                int k = dy*3 + dx;
                PA[k] = pack2(patch[ty + dy][tx + dx],      patch[ty + 8  + dy][tx + dx]);
                PB[k] = pack2(patch[ty + 16 + dy][tx + dx], patch[ty + 24 + dy][tx + dx]);
            }
#pragma unroll
        for (int o = 0; o < 8; o++) {
            const ull* w = &wsm[(o*64 + ic) * 9];
#pragma unroll
            for (int k = 0; k < 9; k++) {
                ull w2 = w[k];
                accA[o] = fma2(PA[k], w2, accA[o]);
                accB[o] = fma2(PB[k], w2, accB[o]);
            }
        }
    }

#pragma unroll
    for (int o = 0; o < 8; o++) {
        int oc = ocg*8 + o;
        float bias = g_wb[(size_t)r * 18464 + 18432 + oc];
        float v0, v1, v2, v3;
        unpack2(accA[o], v0, v1);
        unpack2(accB[o], v2, v3);
        float vv[4] = {v0, v1, v2, v3};
        size_t base = (size_t)(b*96 + 64 + oc) * 65536;
#pragma unroll
        for (int k = 0; k < 4; k++)
            out[base + (size_t)(gy0 + ty + 8*k) * 256 + gx0 + tx] = vv[k] + bias;
    }
}

// ---------------- passthrough copy: out[:, 0:64] = feature -----------------
__global__ void copy_feat_kernel(const float4* __restrict__ f, float4* __restrict__ out)
{
    int i = blockIdx.x * 256 + threadIdx.x;    // 4,194,304 float4 total
    if (i < 4194304) {
        int b = i >> 20;                        // 1,048,576 float4 per batch (64 ch)
        int rem = i & ((1 << 20) - 1);
        out[(size_t)b * 1572864 + rem] = f[i];  // 96 ch * 65536 / 4 per batch
    }
}

// ---------------- launch ---------------------------------------------------
extern "C" void kernel_launch(void* const* d_in, const int* in_sizes, int n_in,
                              void* d_out, int out_size)
{
    const float* feature = (const float*)d_in[0];
    const float* rw1 = (const float*)d_in[1];
    const float* rb1 = (const float*)d_in[2];
    const float* rw2 = (const float*)d_in[3];
    const float* rb2 = (const float*)d_in[4];
    const float* fw1 = (const float*)d_in[5];
    const float* fb1 = (const float*)d_in[6];
    const float* fw2 = (const float*)d_in[7];
    const float* fb2 = (const float*)d_in[8];
    const float* fw3 = (const float*)d_in[9];
    const float* fb3 = (const float*)d_in[10];
    float* out = (float*)d_out;

    conv1_kernel<<<dim3(8, 8, 32), dim3(32, 8)>>>(feature, rw1, rb1);
    conv2_kernel<<<dim3(8, 8, 4),  dim3(32, 8)>>>(rw2, rb2);
    pool_kernel<<<64, 256>>>();

    // FC1: 64x1024 @ 1024x2048, split-K 8
    gemm_sk_kernel<<<dim3(32, 8), 128>>>(fw1, 1024, 2048, 128, 0);
    gemm_reduce_kernel<<<(64*512 + 255)/256, 256>>>(fb1, 2048, 8, 1, 0);
    // FC2: 64x2048 @ 2048x2048, split-K 8
    gemm_sk_kernel<<<dim3(32, 8), 128>>>(fw2, 2048, 2048, 256, 1);
    gemm_reduce_kernel<<<(64*512 + 255)/256, 256>>>(fb2, 2048, 8, 1, 1);
    // FC3: 64x2048 @ 2048x18464, split-K 2
    gemm_sk_kernel<<<dim3(289, 2), 128>>>(fw3, 2048, 18464, 1024, 2);
    gemm_reduce_kernel<<<(64*4616 + 255)/256, 256>>>(fb3, 18464, 2, 0, 2);

    dynconv_kernel<<<dim3(2, 2, 256), dim3(32, 8)>>>(feature, out);
    copy_feat_kernel<<<16384, 256>>>((const float4*)feature, (float4*)out);
}

// round 3
// speedup vs baseline: 1.6976x; 1.2279x over previous
#include <cuda_runtime.h>
#include <math.h>

// Problem constants
// B=4, C=64, H=W=256, N_SPLIT=4 (T=16), RED_FC=32, OUT_NC=32, K=3, FMN1=FMN2=2048
// wsize = 32*64*9 = 18432, wb row = 18464

typedef unsigned long long ull;

// ---------------- scratch (device globals; no runtime allocation) ----------
__device__ float g_h[4*64*256*256];       // conv1 output (leaky-relu'd)
__device__ float g_adap[4*256*256];       // tanh(conv2)
__device__ float g_gram[64*1024];         // pooled grams
__device__ float g_fc1[64*2048];
__device__ float g_fc2[64*2048];
__device__ float g_wb[64*18464];          // dynamic weights + bias
__device__ float g_part[9453568];         // split-K partials (max: 8 x 64 x 18464)

// ---------------- f32x2 helpers (sm_103a packed fp32 FMA) ------------------
__device__ __forceinline__ ull pack2(float lo, float hi) {
    ull d;
    asm("mov.b64 %0, {%1, %2};" : "=l"(d) : "f"(lo), "f"(hi));
    return d;
}
__device__ __forceinline__ void unpack2(ull d, float& lo, float& hi) {
    asm("mov.b64 {%0, %1}, %2;" : "=f"(lo), "=f"(hi) : "l"(d));
}
__device__ __forceinline__ ull fma2(ull a, ull b, ull c) {
    ull d;
    asm("fma.rn.f32x2 %0, %1, %2, %3;" : "=l"(d) : "l"(a), "l"(b), "l"(c));
    return d;
}

// ---------------- patch pipeline helpers -----------------------------------
// 34x34 halo patch, 256 threads, 5 elements per thread.
__device__ __forceinline__ void ldpatch(const float* __restrict__ fp,
                                        int y0, int x0, int tid, float* pre)
{
#pragma unroll
    for (int r = 0; r < 5; r++) {
        int i = tid + 256*r;
        float v = 0.f;
        if (i < 1156) {
            int py = i / 34, px = i - py*34;
            int gy = y0 - 1 + py, gx = x0 - 1 + px;
            if ((unsigned)gy < 256u && (unsigned)gx < 256u) v = __ldg(&fp[gy*256 + gx]);
        }
        pre[r] = v;
    }
}
__device__ __forceinline__ void stpatch(float (*buf)[35], int tid, const float* pre)
{
#pragma unroll
    for (int r = 0; r < 5; r++) {
        int i = tid + 256*r;
        if (i < 1156) buf[i / 34][i - (i/34)*34] = pre[r];
    }
}

// ---------------- conv1: 64->64 3x3 pad1 + leaky relu ----------------------
// grid (8,8,32): x-tile, y-tile, z = b*8 + ocg (8 output chans per block)
// block (32,8): each thread computes 4 pixels. Double-buffered patch, 1 bar/ic.
__global__ __launch_bounds__(256) void conv1_kernel(
    const float* __restrict__ feat,
    const float* __restrict__ rw1,
    const float* __restrict__ rb1)
{
    __shared__ ull wsm[8*64*9];          // splatted (w,w) pairs, 36 KB
    __shared__ float patch[2][34][35];

    int b = blockIdx.z >> 3, ocg = blockIdx.z & 7;
    int x0 = blockIdx.x * 32, y0 = blockIdx.y * 32;
    int tx = threadIdx.x, ty = threadIdx.y;
    int tid = ty * 32 + tx;

    const float* wbase = rw1 + ocg * (8*64*9);
    for (int i = tid; i < 8*64*9; i += 256) {
        float w = wbase[i];
        wsm[i] = pack2(w, w);
    }

    const float* fbase = feat + (size_t)(b*64) * 65536;
    float pre[5];
    ldpatch(fbase, y0, x0, tid, pre);
    stpatch(patch[0], tid, pre);

    ull accA[8], accB[8];
#pragma unroll
    for (int o = 0; o < 8; o++) { accA[o] = 0ull; accB[o] = 0ull; }

    __syncthreads();

    for (int ic = 0; ic < 64; ic++) {
        int p = ic & 1;
        if (ic < 63) ldpatch(fbase + (size_t)(ic+1)*65536, y0, x0, tid, pre);

        ull PA[9], PB[9];
#pragma unroll
        for (int dy = 0; dy < 3; dy++)
#pragma unroll
            for (int dx = 0; dx < 3; dx++) {
                int k = dy*3 + dx;
                PA[k] = pack2(patch[p][ty + dy][tx + dx],      patch[p][ty + 8  + dy][tx + dx]);
                PB[k] = pack2(patch[p][ty + 16 + dy][tx + dx], patch[p][ty + 24 + dy][tx + dx]);
            }
#pragma unroll
        for (int o = 0; o < 8; o++) {
            const ull* w = &wsm[(o*64 + ic) * 9];
#pragma unroll
            for (int k = 0; k < 9; k++) {
                ull w2 = w[k];
                accA[o] = fma2(PA[k], w2, accA[o]);
                accB[o] = fma2(PB[k], w2, accB[o]);
            }
        }
        if (ic < 63) stpatch(patch[p ^ 1], tid, pre);
        __syncthreads();
    }

#pragma unroll
    for (int o = 0; o < 8; o++) {
        int oc = ocg*8 + o;
        float bias = rb1[oc];
        float v0, v1, v2, v3;
        unpack2(accA[o], v0, v1);
        unpack2(accB[o], v2, v3);
        float vv[4] = {v0, v1, v2, v3};
        size_t base = (size_t)(b*64 + oc) * 65536;
#pragma unroll
        for (int k = 0; k < 4; k++) {
            float v = vv[k] + bias;
            v = (v >= 0.f) ? v : 0.2f * v;
            g_h[base + (size_t)(y0 + ty + 8*k) * 256 + x0 + tx] = v;
        }
    }
}

// ---------------- conv2: 64->1 3x3 pad1 + tanh -----------------------------
__global__ __launch_bounds__(256) void conv2_kernel(
    const float* __restrict__ rw2, const float* __restrict__ rb2)
{
    __shared__ float wsm[576];
    __shared__ float patch[2][34][35];
    int b = blockIdx.z;
    int x0 = blockIdx.x * 32, y0 = blockIdx.y * 32;
    int tx = threadIdx.x, ty = threadIdx.y;
    int tid = ty * 32 + tx;
    for (int i = tid; i < 576; i += 256) wsm[i] = rw2[i];
    float acc[4] = {0.f, 0.f, 0.f, 0.f};

    const float* fbase = g_h + (size_t)(b*64) * 65536;
    float pre[5];
    ldpatch(fbase, y0, x0, tid, pre);
    stpatch(patch[0], tid, pre);
    __syncthreads();

    for (int ic = 0; ic < 64; ic++) {
        int p = ic & 1;
        if (ic < 63) ldpatch(fbase + (size_t)(ic+1)*65536, y0, x0, tid, pre);
#pragma unroll
        for (int k = 0; k < 4; k++) {
            float s = acc[k];
#pragma unroll
            for (int dy = 0; dy < 3; dy++)
#pragma unroll
                for (int dx = 0; dx < 3; dx++)
                    s += patch[p][ty + 8*k + dy][tx + dx] * wsm[ic*9 + dy*3 + dx];
            acc[k] = s;
        }
        if (ic < 63) stpatch(patch[p ^ 1], tid, pre);
        __syncthreads();
    }
    float bias = rb2[0];
#pragma unroll
    for (int k = 0; k < 4; k++)
        g_adap[((size_t)b*256 + y0 + ty + 8*k) * 256 + x0 + tx] = tanhf(acc[k] + bias);
}

// ---------------- adaptive pool per tile -> gram ---------------------------
__global__ void pool_kernel()
{
    __shared__ float win[66][67];
    int r = blockIdx.x;
    int b = r >> 4, t = r & 15;
    int ti = t >> 2, tj = t & 3;
    int tid = threadIdx.x;
    for (int i = tid; i < 66*66; i += 256) {
        int h = i / 66, w = i % 66;
        int gy = ti*64 - 1 + h, gx = tj*64 - 1 + w;
        float v = 0.f;
        if ((unsigned)gy < 256u && (unsigned)gx < 256u)
            v = g_adap[((size_t)b*256 + gy) * 256 + gx];
        win[h][w] = v;
    }
    __syncthreads();
    for (int i = tid; i < 1024; i += 256) {
        int p = i >> 5, q = i & 31;
        int sp = (p*66) >> 5, ep = ((p+1)*66 + 31) >> 5;
        int sq = (q*66) >> 5, eq = ((q+1)*66 + 31) >> 5;
        float s = 0.f;
        for (int h = sp; h < ep; h++)
            for (int w = sq; w < eq; w++)
                s += win[h][w];
        g_gram[r*1024 + i] = s / (float)((ep - sp) * (eq - sq));
    }
}

// ---------------- split-K GEMM: part[s] = A(64xKC chunk) @ B ---------------
// grid (ceil(N/64), nsplit), block 128. Thread tile: 4 M-rows x 8 N-cols.
__global__ __launch_bounds__(128) void gemm_sk_kernel(
    const float* __restrict__ Bm, int K, int N, int KC, int stage)
{
    const float* __restrict__ A = (stage == 0) ? g_gram : (stage == 1) ? g_fc1 : g_fc2;

    __shared__ float  As[16][65];
    __shared__ float4 Bs[16][16];

    int n0 = blockIdx.x * 64;
    int k0 = blockIdx.y * KC;
    int tid = threadIdx.x;
    int tx = tid & 7;        // 8 col groups of 8
    int ty = tid >> 3;       // 16 row groups of 4

    ull acc[4][4];
#pragma unroll
    for (int u = 0; u < 4; u++)
#pragma unroll
        for (int v = 0; v < 4; v++) acc[u][v] = 0ull;

    for (int kc = 0; kc < KC; kc += 16) {
        int kb = k0 + kc;
        __syncthreads();
#pragma unroll
        for (int r = 0; r < 2; r++) {
            int i = tid * 2 + r;
            int m  = i >> 2;
            int kg = (i & 3) * 4;
            float4 v = *(const float4*)&A[(size_t)m * K + kb + kg];
            As[kg+0][m] = v.x; As[kg+1][m] = v.y;
            As[kg+2][m] = v.z; As[kg+3][m] = v.w;
        }
#pragma unroll
        for (int r = 0; r < 2; r++) {
            int i = tid * 2 + r;
            int kk = i >> 4;
            int f  = i & 15;
            int col = n0 + f * 4;
            float4 v = make_float4(0.f, 0.f, 0.f, 0.f);
            if (col < N) v = *(const float4*)&Bm[(size_t)(kb + kk) * N + col];
            Bs[kk][f] = v;
        }
        __syncthreads();

#pragma unroll
        for (int kk = 0; kk < 16; kk++) {
            ull a2[4];
#pragma unroll
            for (int u = 0; u < 4; u++) {
                float a = As[kk][ty*4 + u];
                a2[u] = pack2(a, a);
            }
            const ull* bp = (const ull*)&Bs[kk][tx*2];
            ull b2[4];
#pragma unroll
            for (int v = 0; v < 4; v++) b2[v] = bp[v];
#pragma unroll
            for (int u = 0; u < 4; u++)
#pragma unroll
                for (int v = 0; v < 4; v++)
                    acc[u][v] = fma2(b2[v], a2[u], acc[u][v]);
        }
    }

    int s = blockIdx.y;
#pragma unroll
    for (int u = 0; u < 4; u++) {
        int row = ty*4 + u;
#pragma unroll
        for (int v = 0; v < 4; v++) {
            int col = n0 + tx*8 + v*2;
            if (col < N) {
                float lo, hi;
                unpack2(acc[u][v], lo, hi);
                float* p = &g_part[((size_t)(s*64 + row)) * N + col];
                p[0] = lo; p[1] = hi;
            }
        }
    }
}

// ---------------- split-K reduce + bias + activation -----------------------
__global__ void gemm_reduce_kernel(const float* __restrict__ bias,
                                   int N, int nsplit, int relu, int stage)
{
    float* out = (stage == 0) ? g_fc1 : (stage == 1) ? g_fc2 : g_wb;
    int nv = N >> 2;
    int idx = blockIdx.x * 256 + threadIdx.x;
    if (idx >= 64 * nv) return;
    int m = idx / nv, f = idx - m * nv;
    float4 s = make_float4(0.f, 0.f, 0.f, 0.f);
    for (int sp = 0; sp < nsplit; sp++) {
        const float4* p = (const float4*)&g_part[(size_t)(sp*64 + m) * N];
        float4 v = p[f];
        s.x += v.x; s.y += v.y; s.z += v.z; s.w += v.w;
    }
    float4 bv = ((const float4*)bias)[f];
    s.x += bv.x; s.y += bv.y; s.z += bv.z; s.w += bv.w;
    if (relu) {
        s.x = fmaxf(s.x, 0.f); s.y = fmaxf(s.y, 0.f);
        s.z = fmaxf(s.z, 0.f); s.w = fmaxf(s.w, 0.f);
    }
    ((float4*)out)[(size_t)m * nv + f] = s;
}

// ---------------- dynamic per-tile conv (64->32, VALID on 66x66 window) ----
__global__ __launch_bounds__(256) void dynconv_kernel(
    const float* __restrict__ feat, float* __restrict__ out)
{
    __shared__ ull wsm[8*64*9];
    __shared__ float patch[2][34][35];

    int idx = blockIdx.z;
    int ocg = idx & 3;
    int r = idx >> 2;                       // b*16 + t
    int b = r >> 4, t = r & 15;
    int ti = t >> 2, tj = t & 3;
    int gy0 = ti*64 + blockIdx.y * 32;
    int gx0 = tj*64 + blockIdx.x * 32;
    int tx = threadIdx.x, ty = threadIdx.y;
    int tid = ty * 32 + tx;

    const float* wrow = g_wb + (size_t)r * 18464 + ocg * (8*576);
    for (int i = tid; i < 4608; i += 256) {
        float w = wrow[i];
        wsm[i] = pack2(w, w);
    }

    const float* fbase = feat + (size_t)(b*64) * 65536;
    float pre[5];
    ldpatch(fbase, gy0, gx0, tid, pre);
    stpatch(patch[0], tid, pre);

    ull accA[8], accB[8];
#pragma unroll
    for (int o = 0; o < 8; o++) { accA[o] = 0ull; accB[o] = 0ull; }

    __syncthreads();

    for (int ic = 0; ic < 64; ic++) {
        int p = ic & 1;
        if (ic < 63) ldpatch(fbase + (size_t)(ic+1)*65536, gy0, gx0, tid, pre);

        ull PA[9], PB[9];
#pragma unroll
        for (int dy = 0; dy < 3; dy++)
#pragma unroll
            for (int dx = 0; dx < 3; dx++) {
                int k = dy*3 + dx;
                PA[k] = pack2(patch[p][ty + dy][tx + dx],      patch[p][ty + 8  + dy][tx + dx]);
                PB[k] = pack2(patch[p][ty + 16 + dy][tx + dx], patch[p][ty + 24 + dy][tx + dx]);
            }
#pragma unroll
        for (int o = 0; o < 8; o++) {
            const ull* w = &wsm[(o*64 + ic) * 9];
#pragma unroll
            for (int k = 0; k < 9; k++) {
                ull w2 = w[k];
                accA[o] = fma2(PA[k], w2, accA[o]);
                accB[o] = fma2(PB[k], w2, accB[o]);
            }
        }
        if (ic < 63) stpatch(patch[p ^ 1], tid, pre);
        __syncthreads();
    }

#pragma unroll
    for (int o = 0; o < 8; o++) {
        int oc = ocg*8 + o;
        float bias = g_wb[(size_t)r * 18464 + 18432 + oc];
        float v0, v1, v2, v3;
        unpack2(accA[o], v0, v1);
        unpack2(accB[o], v2, v3);
        float vv[4] = {v0, v1, v2, v3};
        size_t base = (size_t)(b*96 + 64 + oc) * 65536;
#pragma unroll
        for (int k = 0; k < 4; k++)
            out[base + (size_t)(gy0 + ty + 8*k) * 256 + gx0 + tx] = vv[k] + bias;
    }
}

// ---------------- passthrough copy: out[:, 0:64] = feature -----------------
__global__ void copy_feat_kernel(const float4* __restrict__ f, float4* __restrict__ out)
{
    int i = blockIdx.x * 256 + threadIdx.x;    // 4,194,304 float4 total
    if (i < 4194304) {
        int b = i >> 20;
        int rem = i & ((1 << 20) - 1);
        out[(size_t)b * 1572864 + rem] = f[i];
    }
}

// ---------------- launch ---------------------------------------------------
extern "C" void kernel_launch(void* const* d_in, const int* in_sizes, int n_in,
                              void* d_out, int out_size)
{
    const float* feature = (const float*)d_in[0];
    const float* rw1 = (const float*)d_in[1];
    const float* rb1 = (const float*)d_in[2];
    const float* rw2 = (const float*)d_in[3];
    const float* rb2 = (const float*)d_in[4];
    const float* fw1 = (const float*)d_in[5];
    const float* fb1 = (const float*)d_in[6];
    const float* fw2 = (const float*)d_in[7];
    const float* fb2 = (const float*)d_in[8];
    const float* fw3 = (const float*)d_in[9];
    const float* fb3 = (const float*)d_in[10];
    float* out = (float*)d_out;

    conv1_kernel<<<dim3(8, 8, 32), dim3(32, 8)>>>(feature, rw1, rb1);
    conv2_kernel<<<dim3(8, 8, 4),  dim3(32, 8)>>>(rw2, rb2);
    pool_kernel<<<64, 256>>>();

    // FC1: 64x1024 @ 1024x2048, split-K 16
    gemm_sk_kernel<<<dim3(32, 16), 128>>>(fw1, 1024, 2048, 64, 0);
    gemm_reduce_kernel<<<(64*512 + 255)/256, 256>>>(fb1, 2048, 16, 1, 0);
    // FC2: 64x2048 @ 2048x2048, split-K 16
    gemm_sk_kernel<<<dim3(32, 16), 128>>>(fw2, 2048, 2048, 128, 1);
    gemm_reduce_kernel<<<(64*512 + 255)/256, 256>>>(fb2, 2048, 16, 1, 1);
    // FC3: 64x2048 @ 2048x18464, split-K 8
    gemm_sk_kernel<<<dim3(289, 8), 128>>>(fw3, 2048, 18464, 256, 2);
    gemm_reduce_kernel<<<(64*4616 + 255)/256, 256>>>(fb3, 18464, 8, 0, 2);

    dynconv_kernel<<<dim3(2, 2, 256), dim3(32, 8)>>>(feature, out);
    copy_feat_kernel<<<16384, 256>>>((const float4*)feature, (float4*)out);
}